// round 2
// baseline (speedup 1.0000x reference)
#include <cuda_runtime.h>
#include <math.h>

#define TT 8192
#define HH 512

// ---------------- scratch ----------------
__device__ float g_h1[(TT + 1) * HH];   // layer-1 hidden seq, slot 0 = h0[0]
__device__ float g_h2[(TT + 1) * HH];   // layer-2 hidden seq, slot 0 = h0[1]
__device__ int   g_f1[HH];              // per-element flags for layer1: value = last step+1
__device__ int   g_f2[HH];              // per-element flags for layer2

// ---------------- sync primitives ----------------
__device__ __forceinline__ int ld_acq(const int* p) {
    int v;
    asm volatile("ld.acquire.gpu.global.b32 %0, [%1];" : "=r"(v) : "l"(p) : "memory");
    return v;
}
__device__ __forceinline__ void st_rel(int* p, int v) {
    asm volatile("st.release.gpu.global.b32 [%0], %1;" :: "l"(p), "r"(v) : "memory");
}
// wait until all 4 consecutive flags >= tgt
__device__ __forceinline__ void poll4(const int* f, int tgt) {
    while (true) {
        int a = ld_acq(f + 0), b = ld_acq(f + 1);
        int c = ld_acq(f + 2), d = ld_acq(f + 3);
        if (min(min(a, b), min(c, d)) >= tgt) return;
    }
}

__device__ __forceinline__ float sigmoidf_(float x) {
    return 1.0f / (1.0f + expf(-x));
}
__device__ __forceinline__ float logsigf_(float z) {
    if (z >= 0.0f) return -log1pf(expf(-z));
    return z - log1pf(expf(z));
}

// ---------------- init ----------------
__global__ void init_kernel(const float* __restrict__ h0) {
    int i = blockIdx.x * blockDim.x + threadIdx.x;
    if (i < HH) {
        g_f1[i] = 0;
        g_f2[i] = 0;
        g_h1[i] = h0[i];
        g_h2[i] = h0[HH + i];
    }
}

// ---------------- persistent pipelined LSTM ----------------
// 129 blocks x 256 threads.
//   blocks [0,64):   layer 1 (8 outputs each)
//   blocks [64,128): layer 2 (8 outputs each)
//   block 128:       head + BCE loss
// Layer thread map: tt = r*8 + s; r=(gate*8+jj) in 0..31; s in 0..7.
// Thread holds cols [s*64, s*64+64) of W_ih[row] and W_hh[row] in registers.
__global__ void __launch_bounds__(256, 1) lstm_kernel(
    const float* __restrict__ x,
    const float* __restrict__ truth,
    const float* __restrict__ c0,
    const float* __restrict__ Wih0, const float* __restrict__ Whh0,
    const float* __restrict__ bih0, const float* __restrict__ bhh0,
    const float* __restrict__ Wih1, const float* __restrict__ Whh1,
    const float* __restrict__ bih1, const float* __restrict__ bhh1,
    const float* __restrict__ Whead, const float* __restrict__ bhead,
    float* __restrict__ out)
{
    const int b = blockIdx.x;
    const int tt = threadIdx.x;

    // ================= HEAD + LOSS =================
    if (b == 128) {
        float w0[16], w1[16];
        if (tt < 32) {
#pragma unroll
            for (int i = 0; i < 16; i++) {
                w0[i] = Whead[i * 32 + tt];
                w1[i] = Whead[HH + i * 32 + tt];
            }
        }
        const float bb0 = bhead[0], bb1 = bhead[1];
        double acc = 0.0;
        const float* hrow = g_h2 + HH;
        for (int t = 0; t < TT; t++, hrow += HH) {
            if (tt < 64) {
                const int* f = g_f2 + tt * 8;
                while (true) {
                    int m = ld_acq(f + 0);
                    m = min(m, ld_acq(f + 1)); m = min(m, ld_acq(f + 2));
                    m = min(m, ld_acq(f + 3)); m = min(m, ld_acq(f + 4));
                    m = min(m, ld_acq(f + 5)); m = min(m, ld_acq(f + 6));
                    m = min(m, ld_acq(f + 7));
                    if (m >= t + 1) break;
                }
            }
            __syncthreads();
            if (tt < 32) {
                float s0 = 0.f, s1 = 0.f;
#pragma unroll
                for (int i = 0; i < 16; i++) {
                    float hv = __ldcg(hrow + i * 32 + tt);
                    s0 = fmaf(w0[i], hv, s0);
                    s1 = fmaf(w1[i], hv, s1);
                }
#pragma unroll
                for (int m = 16; m >= 1; m >>= 1) {
                    s0 += __shfl_xor_sync(0xffffffffu, s0, m);
                    s1 += __shfl_xor_sync(0xffffffffu, s1, m);
                }
                if (tt == 0) {
                    float z0 = s0 + bb0, z1 = s1 + bb1;
                    float y0 = truth[t * 2 + 0], y1 = truth[t * 2 + 1];
                    float t0 = y0 * fmaxf(logsigf_(z0), -100.0f)
                             + (1.0f - y0) * fmaxf(logsigf_(-z0), -100.0f);
                    float t1 = y1 * fmaxf(logsigf_(z1), -100.0f)
                             + (1.0f - y1) * fmaxf(logsigf_(-z1), -100.0f);
                    acc += (double)t0 + (double)t1;
                }
            }
        }
        if (tt == 0) out[0] = (float)(-acc / (double)(TT * 2));
        return;
    }

    // ================= LSTM layer blocks =================
    const int role = b >> 6;            // 0 = layer 1, 1 = layer 2
    const int j0   = (b & 63) * 8;
    const int r    = tt >> 3;           // row 0..31
    const int s    = tt & 7;            // k-slice 0..7 (64 cols each)
    const int gate = r >> 3;
    const int jj   = r & 7;

    const float* WA = role ? Wih1 : Wih0;
    const float* WB = role ? Whh1 : Whh0;
    const long rowOff = (long)(gate * HH + j0 + jj) * HH;

    // register-resident weights, rotation-matched to the LDS schedule
    float4 wA[16], wB[16];
#pragma unroll
    for (int i = 0; i < 16; i++) {
        int col = s * 64 + (((i + s) & 15) << 2);
        wA[i] = __ldg((const float4*)(WA + rowOff + col));
        wB[i] = __ldg((const float4*)(WB + rowOff + col));
    }

    float bsum0 = 0.f, bsum1 = 0.f, bsum2 = 0.f, bsum3 = 0.f, c = 0.f;
    if (tt < 8) {
        const float* bi = role ? bih1 : bih0;
        const float* bh = role ? bhh1 : bhh0;
        bsum0 = bi[0 * HH + j0 + tt] + bh[0 * HH + j0 + tt];
        bsum1 = bi[1 * HH + j0 + tt] + bh[1 * HH + j0 + tt];
        bsum2 = bi[2 * HH + j0 + tt] + bh[2 * HH + j0 + tt];
        bsum3 = bi[3 * HH + j0 + tt] + bh[3 * HH + j0 + tt];
        c = c0[role * HH + j0 + tt];
    }

    __shared__ float vecA[HH];   // input vector  (x[t] or h1[t])
    __shared__ float vecB[HH];   // own h[t-1]
    __shared__ float gsum[32];

    float* myOut      = role ? g_h2 : g_h1;
    int*   myFlag     = role ? g_f2 : g_f1;
    const float* srcA = role ? (g_h1 + HH) : x;       // advances by HH per step
    const float* srcB = role ? g_h2 : g_h1;           // h[t-1], advances by HH

    for (int t = 0; t < TT; t++, srcA += HH, srcB += HH) {
        // ---- poll + stage (poller == stager, per-element flags) ----
        if (tt < 128) {
            if (role) poll4(g_f1 + tt * 4, t + 1);    // h1[t] ready
            float4 v = __ldcg((const float4*)(srcA + tt * 4));
            *(float4*)(vecA + tt * 4) = v;
        } else {
            int u = tt - 128;
            poll4(myFlag + u * 4, t);                 // own h[t-1] ready (t=0 trivially)
            float4 v = __ldcg((const float4*)(srcB + u * 4));
            *(float4*)(vecB + u * 4) = v;
        }
        __syncthreads();

        // ---- fused dual matvec over this thread's 64+64 cols ----
        float acc = 0.f;
#pragma unroll
        for (int i = 0; i < 16; i++) {
            int idx = s * 64 + (((i + s) & 15) << 2);
            float4 va = *(const float4*)(vecA + idx);
            acc = fmaf(wA[i].x, va.x, acc);
            acc = fmaf(wA[i].y, va.y, acc);
            acc = fmaf(wA[i].z, va.z, acc);
            acc = fmaf(wA[i].w, va.w, acc);
        }
#pragma unroll
        for (int i = 0; i < 16; i++) {
            int idx = s * 64 + (((i + s) & 15) << 2);
            float4 vb = *(const float4*)(vecB + idx);
            acc = fmaf(wB[i].x, vb.x, acc);
            acc = fmaf(wB[i].y, vb.y, acc);
            acc = fmaf(wB[i].z, vb.z, acc);
            acc = fmaf(wB[i].w, vb.w, acc);
        }
        acc += __shfl_xor_sync(0xffffffffu, acc, 1);
        acc += __shfl_xor_sync(0xffffffffu, acc, 2);
        acc += __shfl_xor_sync(0xffffffffu, acc, 4);
        if (s == 0) gsum[r] = acc;
        __syncthreads();

        // ---- gates + cell update + per-element release ----
        if (tt < 8) {
            float p0 = gsum[0 * 8 + tt] + bsum0;
            float p1 = gsum[1 * 8 + tt] + bsum1;
            float p2 = gsum[2 * 8 + tt] + bsum2;
            float p3 = gsum[3 * 8 + tt] + bsum3;
            float ig = sigmoidf_(p0);
            float fg = sigmoidf_(p1);
            float gg = tanhf(p2);
            float og = sigmoidf_(p3);
            c = fg * c + ig * gg;
            float h = og * tanhf(c);
            __stcg(myOut + (long)(t + 1) * HH + j0 + tt, h);
            st_rel(myFlag + j0 + tt, t + 1);   // same thread: h store ordered before release
        }
        // no trailing barrier needed: next-iter smem writes are fenced by the
        // two barriers above before any thread can reach them
    }
}

extern "C" void kernel_launch(void* const* d_in, const int* in_sizes, int n_in,
                              void* d_out, int out_size) {
    const float* x     = (const float*)d_in[0];
    const float* truth = (const float*)d_in[1];
    const float* h0    = (const float*)d_in[2];
    const float* c0    = (const float*)d_in[3];
    const float* Wih0  = (const float*)d_in[4];
    const float* Whh0  = (const float*)d_in[5];
    const float* bih0  = (const float*)d_in[6];
    const float* bhh0  = (const float*)d_in[7];
    const float* Wih1  = (const float*)d_in[8];
    const float* Whh1  = (const float*)d_in[9];
    const float* bih1  = (const float*)d_in[10];
    const float* bhh1  = (const float*)d_in[11];
    const float* Whead = (const float*)d_in[12];
    const float* bhead = (const float*)d_in[13];
    float* out = (float*)d_out;

    init_kernel<<<2, 256>>>(h0);
    lstm_kernel<<<129, 256>>>(x, truth, c0,
                              Wih0, Whh0, bih0, bhh0,
                              Wih1, Whh1, bih1, bhh1,
                              Whead, bhead, out);
}

// round 3
// speedup vs baseline: 2.2455x; 2.2455x over previous
#include <cuda_runtime.h>
#include <math.h>

typedef unsigned long long ull;

#define TT 8192
#define HH 512

// ---------------- scratch: packed {flag(hi32), h_bits(lo32)} mailboxes ----------------
// slot k holds h after step k (slot 0 = h0, flag 0). Written flag = k.
__device__ ull g_p1[(TT + 1) * HH];   // layer-1 hidden sequence (packed)
__device__ ull g_p2[(TT + 1) * HH];   // layer-2 hidden sequence (packed)

// ---------------- primitives ----------------
__device__ __forceinline__ ull ld_rlx(const ull* p) {
    ull v;
    asm volatile("ld.relaxed.gpu.global.u64 %0, [%1];" : "=l"(v) : "l"(p) : "memory");
    return v;
}
__device__ __forceinline__ void st_rlx(ull* p, ull v) {
    asm volatile("st.relaxed.gpu.global.u64 [%0], %1;" :: "l"(p), "l"(v) : "memory");
}
__device__ __forceinline__ ull packhf(unsigned flag, float h) {
    return ((ull)flag << 32) | (ull)__float_as_uint(h);
}
__device__ __forceinline__ float lo_f(ull v) { return __uint_as_float((unsigned)v); }
__device__ __forceinline__ unsigned hi_u(ull v) { return (unsigned)(v >> 32); }

// packed dual-fp32 FMA: acc.lo += w.lo*v.lo ; acc.hi += w.hi*v.hi
__device__ __forceinline__ void ffma2(ull& acc, ull w, ull v) {
    asm("fma.rn.f32x2 %0, %1, %2, %0;" : "+l"(acc) : "l"(w), "l"(v));
}
__device__ __forceinline__ float2 unpack2(ull v) {
    float a, b;
    asm("mov.b64 {%0,%1}, %2;" : "=f"(a), "=f"(b) : "l"(v));
    return make_float2(a, b);
}

__device__ __forceinline__ float sigmoidf_(float x) { return 1.0f / (1.0f + expf(-x)); }
__device__ __forceinline__ float logsigf_(float z) {
    if (z >= 0.0f) return -log1pf(expf(-z));
    return z - log1pf(expf(z));
}

// ---------------- clear + seed ----------------
// zero flags of slots 1..TT (both layers), seed slot 0 with h0 (flag 0)
__global__ void clear_kernel(const float* __restrict__ h0) {
    size_t i = (size_t)blockIdx.x * blockDim.x + threadIdx.x;
    if (i < HH) {
        g_p1[i] = packhf(0u, h0[i]);
        g_p2[i] = packhf(0u, h0[HH + i]);
    }
    const size_t N2 = (size_t)TT * HH / 2;   // ull2 granules
    ulonglong2* a = (ulonglong2*)(g_p1 + HH);
    ulonglong2* b = (ulonglong2*)(g_p2 + HH);
    ulonglong2 z; z.x = 0ull; z.y = 0ull;
    size_t stride = (size_t)gridDim.x * blockDim.x;
    for (size_t k = i; k < N2; k += stride) { a[k] = z; b[k] = z; }
}

// ---------------- persistent pipelined LSTM ----------------
// 129 blocks x 256 threads.
//   blocks [0,64):   layer 1 (8 outputs each)
//   blocks [64,128): layer 2 (8 outputs each)
//   block 128:       head + BCE loss
// Layer thread map: tt = p*8 + s; p in 0..31 (row-pair), s in 0..7 (64-col slice).
//   p <  16 -> W_ih rows (2p, 2p+1) of the block's 32-row A set
//   p >= 16 -> W_hh rows (2(p-16), 2(p-16)+1) of the 32-row B set
__global__ void __launch_bounds__(256, 1) lstm_kernel(
    const float* __restrict__ x,
    const float* __restrict__ truth,
    const float* __restrict__ c0,
    const float* __restrict__ Wih0, const float* __restrict__ Whh0,
    const float* __restrict__ bih0, const float* __restrict__ bhh0,
    const float* __restrict__ Wih1, const float* __restrict__ Whh1,
    const float* __restrict__ bih1, const float* __restrict__ bhh1,
    const float* __restrict__ Whead, const float* __restrict__ bhead,
    float* __restrict__ out)
{
    const int b  = blockIdx.x;
    const int tt = threadIdx.x;

    // ================= HEAD + LOSS =================
    if (b == 128) {
        if (tt >= 32) return;
        // lane tt handles h2 elements [16*tt, 16*tt+16)
        float w0[16], w1[16];
#pragma unroll
        for (int i = 0; i < 16; i++) {
            w0[i] = Whead[tt * 16 + i];
            w1[i] = Whead[HH + tt * 16 + i];
        }
        const float bb0 = bhead[0], bb1 = bhead[1];
        double acc = 0.0;
        const ull* pe = g_p2 + HH + tt * 16;   // slot t+1 base, advances by HH
        for (int t = 0; t < TT; t++, pe += HH) {
            const unsigned tgt = (unsigned)(t + 1);
            ull v[16];
            // fused poll+load: re-load any element whose flag isn't current
            bool ok = false;
            while (!ok) {
                ok = true;
#pragma unroll
                for (int i = 0; i < 16; i++) {
                    v[i] = ld_rlx(pe + i);
                    ok &= (hi_u(v[i]) == tgt);
                }
            }
            float s0 = 0.f, s1 = 0.f;
#pragma unroll
            for (int i = 0; i < 16; i++) {
                float hv = lo_f(v[i]);
                s0 = fmaf(w0[i], hv, s0);
                s1 = fmaf(w1[i], hv, s1);
            }
#pragma unroll
            for (int m = 16; m >= 1; m >>= 1) {
                s0 += __shfl_xor_sync(0xffffffffu, s0, m);
                s1 += __shfl_xor_sync(0xffffffffu, s1, m);
            }
            if (tt == 0) {
                float z0 = s0 + bb0, z1 = s1 + bb1;
                float y0 = __ldg(truth + t * 2 + 0), y1 = __ldg(truth + t * 2 + 1);
                float t0 = y0 * fmaxf(logsigf_(z0), -100.0f)
                         + (1.0f - y0) * fmaxf(logsigf_(-z0), -100.0f);
                float t1 = y1 * fmaxf(logsigf_(z1), -100.0f)
                         + (1.0f - y1) * fmaxf(logsigf_(-z1), -100.0f);
                acc += (double)t0 + (double)t1;
            }
        }
        if (tt == 0) out[0] = (float)(-acc / (double)(TT * 2));
        return;
    }

    // ================= LSTM layer blocks =================
    const int role = b >> 6;            // 0 = layer 1, 1 = layer 2
    const int j0   = (b & 63) * 8;
    const int p    = tt >> 3;           // row-pair 0..31
    const int s    = tt & 7;            // col slice 0..7
    const bool isB = (p >= 16);
    const int rr0  = 2 * (p & 15);      // even matrix row 0..30
    const int gate = rr0 >> 3;
    const int jj   = rr0 & 7;

    const float* W = isB ? (role ? Whh1 : Whh0) : (role ? Wih1 : Wih0);
    const size_t growOff = (size_t)(gate * HH + j0 + jj) * HH;   // row rr0; rr0+1 is +HH

    // register-resident weights: 2 rows x 64 cols, rotation-matched to LDS schedule
    ulonglong2 w0[16], w1[16];
#pragma unroll
    for (int i = 0; i < 16; i++) {
        int col = s * 64 + 4 * ((i + s) & 15);
        w0[i] = *(const ulonglong2*)(W + growOff + col);
        w1[i] = *(const ulonglong2*)(W + growOff + HH + col);
    }

    float bsum0 = 0.f, bsum1 = 0.f, bsum2 = 0.f, bsum3 = 0.f, c = 0.f;
    if (tt < 8) {
        const float* bi = role ? bih1 : bih0;
        const float* bh = role ? bhh1 : bhh0;
        bsum0 = bi[0 * HH + j0 + tt] + bh[0 * HH + j0 + tt];
        bsum1 = bi[1 * HH + j0 + tt] + bh[1 * HH + j0 + tt];
        bsum2 = bi[2 * HH + j0 + tt] + bh[2 * HH + j0 + tt];
        bsum3 = bi[3 * HH + j0 + tt] + bh[3 * HH + j0 + tt];
        c = c0[role * HH + j0 + tt];
    }

    __shared__ float vecs[2 * HH];   // [0,512): input vec A ; [512,1024): own h[t-1]
    __shared__ float gsum[64];

    ull* myP = role ? g_p2 : g_p1;
    // staging pointers: thread stages elements {2tt, 2tt+1} of each vector
    const ull* pA = g_p1 + HH + 2 * tt;     // layer2 input: slot t+1 (advances HH/step)
    const ull* pB = myP + 2 * tt;           // own prev:     slot t   (advances HH/step)
    const float2* px = (const float2*)x + tt;  // layer1 input (advances HH/2 float2)

    const int myJ = j0 + tt;                // producer element (tt<8)
    ull* myOut = myP + HH + myJ;            // slot t+1 (advances HH/step)

    for (int t = 0; t < TT; t++, pA += HH, pB += HH, px += HH / 2, myOut += HH) {
        // ---- fused poll+load staging (all 256 threads) ----
        const unsigned tgtA = (unsigned)(t + 1);
        const unsigned tgtB = (unsigned)t;
        float2 va, vb;
        {
            ull a0, a1, b0, b1;
            bool okA = (role == 0), okB = false;
            if (role == 0) va = __ldg(px);
            do {
                if (!okA) {
                    a0 = ld_rlx(pA); a1 = ld_rlx(pA + 1);
                    okA = (hi_u(a0) == tgtA) & (hi_u(a1) == tgtA);
                }
                if (!okB) {
                    b0 = ld_rlx(pB); b1 = ld_rlx(pB + 1);
                    okB = (hi_u(b0) == tgtB) & (hi_u(b1) == tgtB);
                }
            } while (!(okA & okB));
            if (role) va = make_float2(lo_f(a0), lo_f(a1));
            vb = make_float2(lo_f(b0), lo_f(b1));
        }
        ((float2*)vecs)[tt] = va;
        ((float2*)(vecs + HH))[tt] = vb;
        __syncthreads();

        // ---- packed dual-row matvec over this thread's 64-col slice ----
        const float* vbase = vecs + (isB ? HH : 0) + s * 64;
        ull acc0 = 0ull, acc1 = 0ull;
#pragma unroll
        for (int i = 0; i < 16; i++) {
            int idx = 4 * ((i + s) & 15);
            ulonglong2 v = *(const ulonglong2*)(vbase + idx);
            ffma2(acc0, w0[i].x, v.x);
            ffma2(acc0, w0[i].y, v.y);
            ffma2(acc1, w1[i].x, v.x);
            ffma2(acc1, w1[i].y, v.y);
        }
        float2 u0 = unpack2(acc0), u1 = unpack2(acc1);
        float sum0 = u0.x + u0.y;
        float sum1 = u1.x + u1.y;
        sum0 += __shfl_xor_sync(0xffffffffu, sum0, 1);
        sum1 += __shfl_xor_sync(0xffffffffu, sum1, 1);
        sum0 += __shfl_xor_sync(0xffffffffu, sum0, 2);
        sum1 += __shfl_xor_sync(0xffffffffu, sum1, 2);
        sum0 += __shfl_xor_sync(0xffffffffu, sum0, 4);
        sum1 += __shfl_xor_sync(0xffffffffu, sum1, 4);
        if (s == 0) {
            int gr = (isB ? 32 : 0) + rr0;
            gsum[gr]     = sum0;
            gsum[gr + 1] = sum1;
        }
        __syncthreads();

        // ---- gates + cell update + packed release (single 64-bit mailbox store) ----
        if (tt < 8) {
            float p0 = gsum[0 * 8 + tt] + gsum[32 + 0 * 8 + tt] + bsum0;
            float p1 = gsum[1 * 8 + tt] + gsum[32 + 1 * 8 + tt] + bsum1;
            float p2 = gsum[2 * 8 + tt] + gsum[32 + 2 * 8 + tt] + bsum2;
            float p3 = gsum[3 * 8 + tt] + gsum[32 + 3 * 8 + tt] + bsum3;
            float ig = sigmoidf_(p0);
            float fg = sigmoidf_(p1);
            float gg = tanhf(p2);
            float og = sigmoidf_(p3);
            c = fg * c + ig * gg;
            float h = og * tanhf(c);
            st_rlx(myOut, packhf((unsigned)(t + 1), h));
        }
    }
}

extern "C" void kernel_launch(void* const* d_in, const int* in_sizes, int n_in,
                              void* d_out, int out_size) {
    const float* x     = (const float*)d_in[0];
    const float* truth = (const float*)d_in[1];
    const float* h0    = (const float*)d_in[2];
    const float* c0    = (const float*)d_in[3];
    const float* Wih0  = (const float*)d_in[4];
    const float* Whh0  = (const float*)d_in[5];
    const float* bih0  = (const float*)d_in[6];
    const float* bhh0  = (const float*)d_in[7];
    const float* Wih1  = (const float*)d_in[8];
    const float* Whh1  = (const float*)d_in[9];
    const float* bih1  = (const float*)d_in[10];
    const float* bhh1  = (const float*)d_in[11];
    const float* Whead = (const float*)d_in[12];
    const float* bhead = (const float*)d_in[13];
    float* out = (float*)d_out;

    clear_kernel<<<256, 1024>>>(h0);
    lstm_kernel<<<129, 256>>>(x, truth, c0,
                              Wih0, Whh0, bih0, bhh0,
                              Wih1, Whh1, bih1, bhh1,
                              Whead, bhead, out);
}